// round 1
// baseline (speedup 1.0000x reference)
#include <cuda_runtime.h>
#include <cstdint>

// ---------------------------------------------------------------------------
// Problem constants
//   B=32, N=1024  -> T = 32768 tokens
//   d = 256 (embedding), C = 1024 (classes)
// Outputs (concatenated in d_out, fp32):
//   o_cls  (T x C)  = l2norm(x) @ l2norm(e, axis=0)
//   o_seq  (T x C)  = l2norm(x) @ l2norm(w, axis=0)
//   new_db (d x C)  = EMA codebook update
// ---------------------------------------------------------------------------

#define T_TOKENS 32768
#define DIM      256
#define NCLS     1024
#define ALPHA_F  0.9f
#define EPS_F    1.19e-07f

// Scratch (device globals: allocation-free per harness rules)
__device__ float g_x  [(size_t)T_TOKENS * DIM];   // normalized embeddings (row-major T x d)
__device__ float g_wn [DIM * NCLS];               // column-normalized w
__device__ float g_en [DIM * NCLS];               // column-normalized e
__device__ float g_num[DIM * NCLS];               // scatter accumulator
__device__ float g_cnt[NCLS];
__device__ float g_sumA[NCLS];                    // sum of anc per class
__device__ float g_sumNA[NCLS];                   // sum of (1-anc) per class

// ---------------------------------------------------------------------------
// 0) zero the per-call accumulators
// ---------------------------------------------------------------------------
__global__ void zero_kernel() {
    int i = blockIdx.x * blockDim.x + threadIdx.x;
    int stride = gridDim.x * blockDim.x;
    for (int j = i; j < DIM * NCLS; j += stride) g_num[j] = 0.0f;
    if (i < NCLS) { g_cnt[i] = 0.0f; g_sumA[i] = 0.0f; g_sumNA[i] = 0.0f; }
}

// ---------------------------------------------------------------------------
// 1) per-token l2 normalize + class-conditioned scatter (fused)
//    one warp per token; lane handles 8 contiguous dims
// ---------------------------------------------------------------------------
__global__ void norm_x_kernel(const float* __restrict__ emb,
                              const int*   __restrict__ labels,
                              const float* __restrict__ anc)
{
    int gwarp = (blockIdx.x * blockDim.x + threadIdx.x) >> 5;
    int lane  = threadIdx.x & 31;
    if (gwarp >= T_TOKENS) return;

    const float* src = emb + (size_t)gwarp * DIM + lane * 8;
    float4 v0 = *(const float4*)(src);
    float4 v1 = *(const float4*)(src + 4);

    float s = v0.x*v0.x + v0.y*v0.y + v0.z*v0.z + v0.w*v0.w
            + v1.x*v1.x + v1.y*v1.y + v1.z*v1.z + v1.w*v1.w;
    #pragma unroll
    for (int o = 16; o > 0; o >>= 1) s += __shfl_xor_sync(0xFFFFFFFFu, s, o);

    float r = rsqrtf(fmaxf(s, 1e-12f));
    v0.x *= r; v0.y *= r; v0.z *= r; v0.w *= r;
    v1.x *= r; v1.y *= r; v1.z *= r; v1.w *= r;

    float* dst = g_x + (size_t)gwarp * DIM + lane * 8;
    *(float4*)(dst)     = v0;
    *(float4*)(dst + 4) = v1;

    float a = anc[gwarp];
    int   c = labels[gwarp];
    if (a > 0.5f) {
        int d0 = lane * 8;
        atomicAdd(&g_num[(d0 + 0) * NCLS + c], v0.x);
        atomicAdd(&g_num[(d0 + 1) * NCLS + c], v0.y);
        atomicAdd(&g_num[(d0 + 2) * NCLS + c], v0.z);
        atomicAdd(&g_num[(d0 + 3) * NCLS + c], v0.w);
        atomicAdd(&g_num[(d0 + 4) * NCLS + c], v1.x);
        atomicAdd(&g_num[(d0 + 5) * NCLS + c], v1.y);
        atomicAdd(&g_num[(d0 + 6) * NCLS + c], v1.z);
        atomicAdd(&g_num[(d0 + 7) * NCLS + c], v1.w);
    }
    if (lane == 0) {
        atomicAdd(&g_cnt[c],   1.0f);
        atomicAdd(&g_sumA[c],  a);
        atomicAdd(&g_sumNA[c], 1.0f - a);
    }
}

// ---------------------------------------------------------------------------
// 2) column-l2-normalize w and e  (one thread per column)
// ---------------------------------------------------------------------------
__global__ void norm_we_kernel(const float* __restrict__ w,
                               const float* __restrict__ e)
{
    int c = blockIdx.x * blockDim.x + threadIdx.x;   // 0..2047
    if (c >= 2 * NCLS) return;
    const float* src;
    float* dst;
    int col;
    if (c < NCLS) { src = w; dst = g_wn; col = c; }
    else          { src = e; dst = g_en; col = c - NCLS; }

    float s = 0.0f;
    #pragma unroll 8
    for (int d = 0; d < DIM; d++) {
        float v = src[(size_t)d * NCLS + col];
        s += v * v;
    }
    float r = rsqrtf(fmaxf(s, 1e-12f));
    #pragma unroll 8
    for (int d = 0; d < DIM; d++)
        dst[(size_t)d * NCLS + col] = src[(size_t)d * NCLS + col] * r;
}

// ---------------------------------------------------------------------------
// 3) fused dual GEMM: g_x (T x d) @ {g_en, g_wn} (d x C)
//    128x128x16 block tile, 8x8 register tile, 256 threads
//    gridDim = (16, 256): blockIdx.x < 8 -> o_cls (en), else o_seq (wn)
// ---------------------------------------------------------------------------
#define BM 128
#define BN 128
#define BK 16
#define TM 8
#define TN 8

__global__ __launch_bounds__(256)
void gemm_kernel(float* __restrict__ out_cls, float* __restrict__ out_seq)
{
    const int K = DIM;
    const int C = NCLS;

    int n_global = blockIdx.x * BN;        // 0..1920 within 2048 fused columns
    const float* Bp;
    float* O;
    int nb;
    if (n_global < C) { Bp = g_en; O = out_cls; nb = n_global; }
    else              { Bp = g_wn; O = out_seq; nb = n_global - C; }

    int m0 = blockIdx.y * BM;

    __shared__ float As[BK][BM];
    __shared__ float Bs[BK][BN];

    int tid  = threadIdx.x;
    int tcol = tid & 15;   // along N
    int trow = tid >> 4;   // along M

    float acc[TM][TN];
    #pragma unroll
    for (int i = 0; i < TM; i++)
        #pragma unroll
        for (int j = 0; j < TN; j++) acc[i][j] = 0.0f;

    for (int k0 = 0; k0 < K; k0 += BK) {
        // load A tile (128 x 16), store transposed [k][m]
        #pragma unroll
        for (int l = 0; l < 2; l++) {
            int f  = tid + l * 256;          // 0..511 float4 slots
            int r  = f >> 2;                 // 0..127
            int c4 = (f & 3) * 4;            // 0,4,8,12
            float4 v = *(const float4*)(g_x + (size_t)(m0 + r) * K + k0 + c4);
            As[c4 + 0][r] = v.x;
            As[c4 + 1][r] = v.y;
            As[c4 + 2][r] = v.z;
            As[c4 + 3][r] = v.w;
        }
        // load B tile (16 x 128), keep row-major [k][n]
        #pragma unroll
        for (int l = 0; l < 2; l++) {
            int f  = tid + l * 256;
            int r  = f >> 5;                 // 0..15
            int c4 = (f & 31) * 4;           // 0..124
            *(float4*)(&Bs[r][c4]) =
                *(const float4*)(Bp + (size_t)(k0 + r) * C + nb + c4);
        }
        __syncthreads();

        #pragma unroll
        for (int kk = 0; kk < BK; kk++) {
            float ar[TM], br[TN];
            float4 a0 = *(const float4*)(&As[kk][trow * TM]);
            float4 a1 = *(const float4*)(&As[kk][trow * TM + 4]);
            float4 b0 = *(const float4*)(&Bs[kk][tcol * TN]);
            float4 b1 = *(const float4*)(&Bs[kk][tcol * TN + 4]);
            ar[0]=a0.x; ar[1]=a0.y; ar[2]=a0.z; ar[3]=a0.w;
            ar[4]=a1.x; ar[5]=a1.y; ar[6]=a1.z; ar[7]=a1.w;
            br[0]=b0.x; br[1]=b0.y; br[2]=b0.z; br[3]=b0.w;
            br[4]=b1.x; br[5]=b1.y; br[6]=b1.z; br[7]=b1.w;
            #pragma unroll
            for (int i = 0; i < TM; i++)
                #pragma unroll
                for (int j = 0; j < TN; j++)
                    acc[i][j] += ar[i] * br[j];
        }
        __syncthreads();
    }

    // epilogue: vectorized stores
    #pragma unroll
    for (int i = 0; i < TM; i++) {
        size_t row = (size_t)(m0 + trow * TM + i);
        float4* p = (float4*)(O + row * C + nb + tcol * TN);
        p[0] = make_float4(acc[i][0], acc[i][1], acc[i][2], acc[i][3]);
        p[1] = make_float4(acc[i][4], acc[i][5], acc[i][6], acc[i][7]);
    }
}

// ---------------------------------------------------------------------------
// 4) finalize new_db (d x C elementwise)
// ---------------------------------------------------------------------------
__global__ void finalize_kernel(const float* __restrict__ w,
                                const float* __restrict__ e,
                                float* __restrict__ db)
{
    int idx = blockIdx.x * blockDim.x + threadIdx.x;
    if (idx >= DIM * NCLS) return;
    int c = idx & (NCLS - 1);

    float cnt    = g_cnt[c];
    float negAnc = (g_sumA[c]  > 0.5f) ? 1.0f : 0.0f;
    float posAnc = (g_sumNA[c] > 0.5f) ? 1.0f : 0.0f;
    float negCls = (cnt > 0.5f) ? 0.0f : 1.0f;

    float wv = w[idx];
    float ev = e[idx];
    float ema = 0.1f * (g_num[idx] / (cnt + EPS_F));
    db[idx] = ALPHA_F * wv * negAnc + ema + wv * negCls + ev * posAnc;
}

// ---------------------------------------------------------------------------
// launch
// ---------------------------------------------------------------------------
extern "C" void kernel_launch(void* const* d_in, const int* in_sizes, int n_in,
                              void* d_out, int out_size)
{
    const float* emb = (const float*)d_in[0];
    // d_in[1] = ious (unused by outputs)
    const int*   obj = (const int*)  d_in[2];
    const float* anc = (const float*)d_in[3];
    // d_in[4] = cls_labels (unused by outputs)
    const float* w   = (const float*)d_in[5];
    const float* e   = (const float*)d_in[6];

    float* out   = (float*)d_out;
    float* o_cls = out;
    float* o_seq = out + (size_t)T_TOKENS * NCLS;
    float* db    = out + (size_t)2 * T_TOKENS * NCLS;

    zero_kernel<<<512, 256>>>();
    norm_x_kernel<<<(T_TOKENS * 32) / 256, 256>>>(emb, obj, anc);
    norm_we_kernel<<<8, 256>>>(w, e);

    dim3 grid(2 * NCLS / BN, T_TOKENS / BM);  // (16, 256)
    gemm_kernel<<<grid, 256>>>(o_cls, o_seq);

    finalize_kernel<<<(DIM * NCLS) / 256, 256>>>(w, e, db);
}

// round 5
// speedup vs baseline: 4.9727x; 4.9727x over previous
#include <cuda_runtime.h>
#include <cuda_fp16.h>
#include <cstdint>

// ---------------------------------------------------------------------------
// B=32, N=1024 -> T=32768 tokens, d=256, C=1024
// o_cls (T x C) = l2norm(x) @ l2norm(e,0)
// o_seq (T x C) = l2norm(x) @ l2norm(w,0)
// new_db (d x C) = EMA codebook update
// GEMMs: fp16 mma.sync (HMMA) — tcgen05 PTX is rejected by the harness's
// ptxas target (sm_103 family, not sm_103a), so legacy tensor path it is.
// ---------------------------------------------------------------------------

#define T_TOKENS 32768
#define DIM      256
#define NCLS     1024
#define ALPHA_F  0.9f
#define EPS_F    1.19e-07f

// GEMM tiling
#define BM 128
#define BN 128
#define BK 64                       // 64 fp16 = 128 bytes/row (SW128 atom)
#define NCHUNK (DIM / BK)           // 4
#define STAGE  32768                // A 16KB + B 16KB
#define GEMM_SMEM (1024 + 2 * STAGE)

// ---------------- device scratch (allocation-free) -------------------------
__device__ __align__(16) __half g_x16 [(size_t)T_TOKENS * DIM];   // normalized x, fp16
__device__ __align__(16) __half g_bt16[(size_t)2 * NCLS * DIM];   // [class][k]: rows 0..1023 = en, 1024..2047 = wn
__device__ float g_num[DIM * NCLS];
__device__ float g_cnt[NCLS];
__device__ float g_sumA[NCLS];
__device__ float g_sumNA[NCLS];

// ---------------- PTX helpers (all portable, sm_80+) -----------------------
__device__ __forceinline__ uint32_t smem_u32(const void* p) {
    uint32_t a;
    asm("{ .reg .u64 t; cvta.to.shared.u64 t, %1; cvt.u32.u64 %0, t; }" : "=r"(a) : "l"(p));
    return a;
}
__device__ __forceinline__ void cpa16(uint32_t s, const void* g) {
    asm volatile("cp.async.cg.shared.global [%0], [%1], 16;" :: "r"(s), "l"(g));
}
#define CP_COMMIT() asm volatile("cp.async.commit_group;" ::: "memory")
#define CP_WAIT(n)  asm volatile("cp.async.wait_group %0;" :: "n"(n) : "memory")

#define LDSM_X4(r0, r1, r2, r3, addr) \
    asm volatile("ldmatrix.sync.aligned.m8n8.x4.shared.b16 {%0,%1,%2,%3}, [%4];" \
        : "=r"(r0), "=r"(r1), "=r"(r2), "=r"(r3) : "r"(addr))

#define MMA16816(d, a, b) \
    asm volatile("mma.sync.aligned.m16n8k16.row.col.f32.f16.f16.f32 " \
        "{%0,%1,%2,%3},{%4,%5,%6,%7},{%8,%9},{%0,%1,%2,%3};" \
        : "+f"((d)[0]), "+f"((d)[1]), "+f"((d)[2]), "+f"((d)[3]) \
        : "r"((a)[0]), "r"((a)[1]), "r"((a)[2]), "r"((a)[3]), \
          "r"((b)[0]), "r"((b)[1]))

__device__ __forceinline__ uint32_t sw128(uint32_t bo) {
    return bo ^ ((bo >> 3) & 0x70);
}

// ---------------------------------------------------------------------------
// 0) zero accumulators
// ---------------------------------------------------------------------------
__global__ void zero_kernel() {
    int i = blockIdx.x * blockDim.x + threadIdx.x;
    int stride = gridDim.x * blockDim.x;
    for (int j = i; j < DIM * NCLS; j += stride) g_num[j] = 0.0f;
    if (i < NCLS) { g_cnt[i] = 0.0f; g_sumA[i] = 0.0f; g_sumNA[i] = 0.0f; }
}

// ---------------------------------------------------------------------------
// 1) per-token l2 normalize -> fp16 + class-conditioned scatter (fused)
// ---------------------------------------------------------------------------
__global__ void norm_x_kernel(const float* __restrict__ emb,
                              const int*   __restrict__ labels,
                              const float* __restrict__ anc)
{
    int gwarp = (blockIdx.x * blockDim.x + threadIdx.x) >> 5;
    int lane  = threadIdx.x & 31;
    if (gwarp >= T_TOKENS) return;

    const float* src = emb + (size_t)gwarp * DIM + lane * 8;
    float v[8];
    float4 v0 = *(const float4*)(src);
    float4 v1 = *(const float4*)(src + 4);
    v[0]=v0.x; v[1]=v0.y; v[2]=v0.z; v[3]=v0.w;
    v[4]=v1.x; v[5]=v1.y; v[6]=v1.z; v[7]=v1.w;

    float s = 0.f;
    #pragma unroll
    for (int j = 0; j < 8; j++) s += v[j] * v[j];
    #pragma unroll
    for (int o = 16; o > 0; o >>= 1) s += __shfl_xor_sync(0xFFFFFFFFu, s, o);
    float r = rsqrtf(fmaxf(s, 1e-12f));

    union { __half h[8]; float4 f; } H;
    #pragma unroll
    for (int j = 0; j < 8; j++) {
        v[j] *= r;
        H.h[j] = __float2half_rn(v[j]);
    }
    *(float4*)(g_x16 + (size_t)gwarp * DIM + lane * 8) = H.f;

    float a = anc[gwarp];
    int   c = labels[gwarp];
    if (a > 0.5f) {
        int d0 = lane * 8;
        #pragma unroll
        for (int j = 0; j < 8; j++)
            atomicAdd(&g_num[(d0 + j) * NCLS + c], v[j]);
    }
    if (lane == 0) {
        atomicAdd(&g_cnt[c],   1.0f);
        atomicAdd(&g_sumA[c],  a);
        atomicAdd(&g_sumNA[c], 1.0f - a);
    }
}

// ---------------------------------------------------------------------------
// 2) column-l2-normalize e/w -> transposed fp16 codebook [c][k]
//    rows 0..1023 = en (o_cls), rows 1024..2047 = wn (o_seq)
// ---------------------------------------------------------------------------
__global__ void build_bt_kernel(const float* __restrict__ w,
                                const float* __restrict__ e)
{
    int c = blockIdx.x * blockDim.x + threadIdx.x;   // 0..2047
    if (c >= 2 * NCLS) return;
    const float* src = (c < NCLS) ? e : w;
    int col = c & (NCLS - 1);

    float s = 0.0f;
    #pragma unroll 8
    for (int d = 0; d < DIM; d++) {
        float v = src[(size_t)d * NCLS + col];
        s += v * v;
    }
    float r = rsqrtf(fmaxf(s, 1e-12f));
    #pragma unroll 8
    for (int d = 0; d < DIM; d++)
        g_bt16[(size_t)c * DIM + d] =
            __float2half_rn(src[(size_t)d * NCLS + col] * r);
}

// ---------------------------------------------------------------------------
// 3) fp16 HMMA GEMM: tile 128x128, 8 warps (warp tile 64x32), K=256 in
//    4 chunks of 64, cp.async double buffer, SW128 smem + ldmatrix.
//    grid = (256, 16): blockIdx.y < 8 -> o_cls, else o_seq.
// ---------------------------------------------------------------------------
__global__ __launch_bounds__(256)
void gemm_hmma_kernel(float* __restrict__ o_cls, float* __restrict__ o_seq)
{
    extern __shared__ char dsm[];
    const int tid    = threadIdx.x;
    const int lane   = tid & 31;
    const int wid    = tid >> 5;
    const int warp_m = wid & 1;     // 0..1 -> rows wm*64
    const int warp_n = wid >> 1;    // 0..3 -> cols wn*32

    const int m0 = blockIdx.x * BM;
    const int n0 = blockIdx.y * BN;              // fused column space [0,2048)
    float* O = (n0 < NCLS) ? o_cls : o_seq;
    const int ncol0 = n0 & (NCLS - 1);

    uint32_t raw  = smem_u32(dsm);
    uint32_t dynu = (raw + 1023u) & ~1023u;

    // ---- stage loader: chunk k0=c*64 -> stage (A @0, B @16384) ------------
    const int lr  = tid >> 3;       // 0..31
    const int lsg = tid & 7;        // 16B segment in row
    auto load_stage = [&](int chunk, int stage) {
        uint32_t sb = dynu + stage * STAGE;
        const int k0 = chunk * BK;
        #pragma unroll
        for (int i = 0; i < 4; i++) {
            int r = lr + i * 32;                 // 0..127
            uint32_t sw = sw128((uint32_t)(r * 128 + lsg * 16));
            cpa16(sb + sw,         g_x16  + (size_t)(m0 + r) * DIM + k0 + lsg * 8);
            cpa16(sb + 16384 + sw, g_bt16 + (size_t)(n0 + r) * DIM + k0 + lsg * 8);
        }
        CP_COMMIT();
    };

    float acc[4][4][4] = {};   // [mfrag][nfrag][4]

    // ---- compute one 64-K chunk from a stage -------------------------------
    auto compute = [&](uint32_t sb) {
        #pragma unroll
        for (int kk = 0; kk < 4; kk++) {         // k16 steps
            uint32_t a[4][4], b[4][2];
            #pragma unroll
            for (int mf = 0; mf < 4; mf++) {
                int row = warp_m * 64 + mf * 16 + (lane & 15);
                uint32_t bo = (uint32_t)(row * 128 + kk * 32 + ((lane >> 4) * 16));
                LDSM_X4(a[mf][0], a[mf][1], a[mf][2], a[mf][3], sb + sw128(bo));
            }
            #pragma unroll
            for (int bf = 0; bf < 2; bf++) {
                int g = lane >> 3;
                int row = warp_n * 32 + bf * 16 + (g >> 1) * 8 + (lane & 7);
                uint32_t bo = (uint32_t)(row * 128 + kk * 32 + ((g & 1) * 16));
                uint32_t r0, r1, r2, r3;
                LDSM_X4(r0, r1, r2, r3, sb + 16384 + sw128(bo));
                b[bf*2][0] = r0; b[bf*2][1] = r1;
                b[bf*2+1][0] = r2; b[bf*2+1][1] = r3;
            }
            #pragma unroll
            for (int mf = 0; mf < 4; mf++)
                #pragma unroll
                for (int nf = 0; nf < 4; nf++)
                    MMA16816(acc[mf][nf], a[mf], b[nf]);
        }
    };

    // ---- pipeline: 2 stages, 4 chunks --------------------------------------
    load_stage(0, 0);
    load_stage(1, 1);

    CP_WAIT(1); __syncthreads();
    compute(dynu);
    __syncthreads();
    load_stage(2, 0);

    CP_WAIT(1); __syncthreads();
    compute(dynu + STAGE);
    __syncthreads();
    load_stage(3, 1);

    CP_WAIT(1); __syncthreads();
    compute(dynu);

    CP_WAIT(0); __syncthreads();
    compute(dynu + STAGE);

    // ---- epilogue: direct fp32 stores --------------------------------------
    #pragma unroll
    for (int mf = 0; mf < 4; mf++) {
        int row = m0 + warp_m * 64 + mf * 16 + (lane >> 2);
        #pragma unroll
        for (int nf = 0; nf < 4; nf++) {
            int col = ncol0 + warp_n * 32 + nf * 8 + 2 * (lane & 3);
            *(float2*)(O + (size_t)row * NCLS + col) =
                make_float2(acc[mf][nf][0], acc[mf][nf][1]);
            *(float2*)(O + (size_t)(row + 8) * NCLS + col) =
                make_float2(acc[mf][nf][2], acc[mf][nf][3]);
        }
    }
}

// ---------------------------------------------------------------------------
// 4) finalize new_db
// ---------------------------------------------------------------------------
__global__ void finalize_kernel(const float* __restrict__ w,
                                const float* __restrict__ e,
                                float* __restrict__ db)
{
    int idx = blockIdx.x * blockDim.x + threadIdx.x;
    if (idx >= DIM * NCLS) return;
    int c = idx & (NCLS - 1);

    float cnt    = g_cnt[c];
    float negAnc = (g_sumA[c]  > 0.5f) ? 1.0f : 0.0f;
    float posAnc = (g_sumNA[c] > 0.5f) ? 1.0f : 0.0f;
    float negCls = (cnt > 0.5f) ? 0.0f : 1.0f;

    float wv = w[idx];
    float ev = e[idx];
    float ema = 0.1f * (g_num[idx] / (cnt + EPS_F));
    db[idx] = ALPHA_F * wv * negAnc + ema + wv * negCls + ev * posAnc;
}

// ---------------------------------------------------------------------------
// launch
// ---------------------------------------------------------------------------
extern "C" void kernel_launch(void* const* d_in, const int* in_sizes, int n_in,
                              void* d_out, int out_size)
{
    const float* emb = (const float*)d_in[0];
    const int*   obj = (const int*)  d_in[2];
    const float* anc = (const float*)d_in[3];
    const float* w   = (const float*)d_in[5];
    const float* e   = (const float*)d_in[6];

    float* out   = (float*)d_out;
    float* o_cls = out;
    float* o_seq = out + (size_t)T_TOKENS * NCLS;
    float* db    = out + (size_t)2 * T_TOKENS * NCLS;

    cudaFuncSetAttribute(gemm_hmma_kernel,
                         cudaFuncAttributeMaxDynamicSharedMemorySize, GEMM_SMEM);

    zero_kernel<<<512, 256>>>();
    norm_x_kernel<<<(T_TOKENS * 32) / 256, 256>>>(emb, obj, anc);
    build_bt_kernel<<<8, 256>>>(w, e);

    dim3 grid(T_TOKENS / BM, 2 * NCLS / BN);     // (256, 16)
    gemm_hmma_kernel<<<grid, 256, GEMM_SMEM>>>(o_cls, o_seq);

    finalize_kernel<<<(DIM * NCLS) / 256, 256>>>(w, e, db);
}

// round 6
// speedup vs baseline: 5.7846x; 1.1633x over previous
#include <cuda_runtime.h>
#include <cuda_fp16.h>
#include <cstdint>

// ---------------------------------------------------------------------------
// B=32, N=1024 -> T=32768 tokens, d=256, C=1024
// o_cls (T x C) = l2norm(x) @ l2norm(e,0)
// o_seq (T x C) = l2norm(x) @ l2norm(w,0)
// new_db (d x C) = EMA codebook update
// GEMMs: fp16 mma.sync (HMMA), 3-stage cp.async pipeline.
// ---------------------------------------------------------------------------

#define T_TOKENS 32768
#define DIM      256
#define NCLS     1024
#define ALPHA_F  0.9f
#define EPS_F    1.19e-07f

// GEMM tiling
#define BM 128
#define BN 128
#define BK 64                       // 64 fp16 = 128 bytes/row (SW128 atom)
#define STAGE  32768                // A 16KB + B 16KB
#define GEMM_SMEM (1024 + 3 * STAGE)

// ---------------- device scratch (allocation-free) -------------------------
__device__ __align__(16) __half g_x16 [(size_t)T_TOKENS * DIM];   // normalized x, fp16
__device__ __align__(16) __half g_bt16[(size_t)2 * NCLS * DIM];   // [class][k]: rows 0..1023 = en, 1024..2047 = wn
__device__ float g_num[DIM * NCLS];
__device__ float g_cnt[NCLS];
__device__ float g_sumA[NCLS];
__device__ float g_sumNA[NCLS];
__device__ float g_colsum[2 * NCLS];   // [0..1023]=e column sq-sums, [1024..2047]=w

// ---------------- PTX helpers (portable, sm_80+) ---------------------------
__device__ __forceinline__ uint32_t smem_u32(const void* p) {
    uint32_t a;
    asm("{ .reg .u64 t; cvta.to.shared.u64 t, %1; cvt.u32.u64 %0, t; }" : "=r"(a) : "l"(p));
    return a;
}
__device__ __forceinline__ void cpa16(uint32_t s, const void* g) {
    asm volatile("cp.async.cg.shared.global [%0], [%1], 16;" :: "r"(s), "l"(g));
}
#define CP_COMMIT() asm volatile("cp.async.commit_group;" ::: "memory")
#define CP_WAIT(n)  asm volatile("cp.async.wait_group %0;" :: "n"(n) : "memory")

#define LDSM_X4(r0, r1, r2, r3, addr) \
    asm volatile("ldmatrix.sync.aligned.m8n8.x4.shared.b16 {%0,%1,%2,%3}, [%4];" \
        : "=r"(r0), "=r"(r1), "=r"(r2), "=r"(r3) : "r"(addr))

#define MMA16816(d, a, b) \
    asm volatile("mma.sync.aligned.m16n8k16.row.col.f32.f16.f16.f32 " \
        "{%0,%1,%2,%3},{%4,%5,%6,%7},{%8,%9},{%0,%1,%2,%3};" \
        : "+f"((d)[0]), "+f"((d)[1]), "+f"((d)[2]), "+f"((d)[3]) \
        : "r"((a)[0]), "r"((a)[1]), "r"((a)[2]), "r"((a)[3]), \
          "r"((b)[0]), "r"((b)[1]))

__device__ __forceinline__ uint32_t sw128(uint32_t bo) {
    return bo ^ ((bo >> 3) & 0x70);
}

// ---------------------------------------------------------------------------
// 0) zero accumulators
// ---------------------------------------------------------------------------
__global__ void zero_kernel() {
    int i = blockIdx.x * blockDim.x + threadIdx.x;
    int stride = gridDim.x * blockDim.x;
    for (int j = i; j < DIM * NCLS; j += stride) g_num[j] = 0.0f;
    if (i < 2 * NCLS) g_colsum[i] = 0.0f;
    if (i < NCLS) { g_cnt[i] = 0.0f; g_sumA[i] = 0.0f; g_sumNA[i] = 0.0f; }
}

// ---------------------------------------------------------------------------
// 1) per-token l2 normalize -> fp16 + class-conditioned scatter (fused)
// ---------------------------------------------------------------------------
__global__ void norm_x_kernel(const float* __restrict__ emb,
                              const int*   __restrict__ labels,
                              const float* __restrict__ anc)
{
    int gwarp = (blockIdx.x * blockDim.x + threadIdx.x) >> 5;
    int lane  = threadIdx.x & 31;
    if (gwarp >= T_TOKENS) return;

    const float* src = emb + (size_t)gwarp * DIM + lane * 8;
    float v[8];
    float4 v0 = *(const float4*)(src);
    float4 v1 = *(const float4*)(src + 4);
    v[0]=v0.x; v[1]=v0.y; v[2]=v0.z; v[3]=v0.w;
    v[4]=v1.x; v[5]=v1.y; v[6]=v1.z; v[7]=v1.w;

    float s = 0.f;
    #pragma unroll
    for (int j = 0; j < 8; j++) s += v[j] * v[j];
    #pragma unroll
    for (int o = 16; o > 0; o >>= 1) s += __shfl_xor_sync(0xFFFFFFFFu, s, o);
    float r = rsqrtf(fmaxf(s, 1e-12f));

    union { __half h[8]; float4 f; } H;
    #pragma unroll
    for (int j = 0; j < 8; j++) {
        v[j] *= r;
        H.h[j] = __float2half_rn(v[j]);
    }
    *(float4*)(g_x16 + (size_t)gwarp * DIM + lane * 8) = H.f;

    float a = anc[gwarp];
    int   c = labels[gwarp];
    if (a > 0.5f) {
        int d0 = lane * 8;
        #pragma unroll
        for (int j = 0; j < 8; j++)
            atomicAdd(&g_num[(d0 + j) * NCLS + c], v[j]);
    }
    if (lane == 0) {
        atomicAdd(&g_cnt[c],   1.0f);
        atomicAdd(&g_sumA[c],  a);
        atomicAdd(&g_sumNA[c], 1.0f - a);
    }
}

// ---------------------------------------------------------------------------
// 2a) column squared-sums of e/w (parallel, coalesced)
//     grid (4, 32, 2): x = 256-col block, y = 8-dim block, z = matrix (0=e,1=w)
// ---------------------------------------------------------------------------
__global__ void colsum_kernel(const float* __restrict__ w,
                              const float* __restrict__ e)
{
    const float* src = (blockIdx.z == 0) ? e : w;
    int col = blockIdx.x * 256 + threadIdx.x;
    int d0  = blockIdx.y * 8;
    float s = 0.0f;
    #pragma unroll
    for (int j = 0; j < 8; j++) {
        float v = src[(size_t)(d0 + j) * NCLS + col];
        s += v * v;
    }
    atomicAdd(&g_colsum[blockIdx.z * NCLS + col], s);
}

// ---------------------------------------------------------------------------
// 2b) scale + transpose + fp16 convert: src [d][c] -> g_bt16 [c][d]
//     grid (32, 8, 2): x = 32-col tile, y = 32-dim tile, z = matrix
//     block 256 = (32 cols, 8 rows)
// ---------------------------------------------------------------------------
__global__ void build_bt_kernel(const float* __restrict__ w,
                                const float* __restrict__ e)
{
    __shared__ float tile[32][33];
    __shared__ float rs[32];

    const float* src = (blockIdx.z == 0) ? e : w;
    const int c0 = blockIdx.x * 32;
    const int d0 = blockIdx.y * 32;
    const int tx = threadIdx.x & 31;
    const int ty = threadIdx.x >> 5;

    if (threadIdx.x < 32)
        rs[threadIdx.x] = rsqrtf(fmaxf(g_colsum[blockIdx.z * NCLS + c0 + threadIdx.x], 1e-12f));

    #pragma unroll
    for (int i = 0; i < 4; i++) {
        int dl = ty + i * 8;
        tile[dl][tx] = src[(size_t)(d0 + dl) * NCLS + c0 + tx];
    }
    __syncthreads();

    #pragma unroll
    for (int i = 0; i < 4; i++) {
        int cl = ty + i * 8;
        float v = tile[tx][cl] * rs[cl];
        g_bt16[(size_t)(blockIdx.z * NCLS + c0 + cl) * DIM + d0 + tx] = __float2half_rn(v);
    }
}

// ---------------------------------------------------------------------------
// 3) fp16 HMMA GEMM: tile 128x128, 8 warps (warp tile 64x32), K=256 in
//    4 chunks of 64, 3-stage cp.async pipeline, SW128 smem + ldmatrix.
//    grid = (256, 16): blockIdx.y < 8 -> o_cls, else o_seq.
// ---------------------------------------------------------------------------
__global__ __launch_bounds__(256)
void gemm_hmma_kernel(float* __restrict__ o_cls, float* __restrict__ o_seq)
{
    extern __shared__ char dsm[];
    const int tid    = threadIdx.x;
    const int lane   = tid & 31;
    const int wid    = tid >> 5;
    const int warp_m = wid & 1;     // 0..1 -> rows wm*64
    const int warp_n = wid >> 1;    // 0..3 -> cols wn*32

    const int m0 = blockIdx.x * BM;
    const int n0 = blockIdx.y * BN;              // fused column space [0,2048)
    float* O = (n0 < NCLS) ? o_cls : o_seq;
    const int ncol0 = n0 & (NCLS - 1);

    uint32_t raw  = smem_u32(dsm);
    uint32_t dynu = (raw + 1023u) & ~1023u;

    // ---- stage loader: chunk k0=c*64 -> stage (A @0, B @16384) ------------
    const int lr  = tid >> 3;       // 0..31
    const int lsg = tid & 7;        // 16B segment in row
    auto load_stage = [&](int chunk, int stage) {
        uint32_t sb = dynu + stage * STAGE;
        const int k0 = chunk * BK;
        #pragma unroll
        for (int i = 0; i < 4; i++) {
            int r = lr + i * 32;                 // 0..127
            uint32_t sw = sw128((uint32_t)(r * 128 + lsg * 16));
            cpa16(sb + sw,         g_x16  + (size_t)(m0 + r) * DIM + k0 + lsg * 8);
            cpa16(sb + 16384 + sw, g_bt16 + (size_t)(n0 + r) * DIM + k0 + lsg * 8);
        }
        CP_COMMIT();
    };

    float acc[4][4][4] = {};   // [mfrag][nfrag][4]

    // ---- compute one 64-K chunk from a stage -------------------------------
    auto compute = [&](uint32_t sb) {
        #pragma unroll
        for (int kk = 0; kk < 4; kk++) {         // k16 steps
            uint32_t a[4][4], b[4][2];
            #pragma unroll
            for (int mf = 0; mf < 4; mf++) {
                int row = warp_m * 64 + mf * 16 + (lane & 15);
                uint32_t bo = (uint32_t)(row * 128 + kk * 32 + ((lane >> 4) * 16));
                LDSM_X4(a[mf][0], a[mf][1], a[mf][2], a[mf][3], sb + sw128(bo));
            }
            #pragma unroll
            for (int bf = 0; bf < 2; bf++) {
                int g = lane >> 3;
                int row = warp_n * 32 + bf * 16 + (g >> 1) * 8 + (lane & 7);
                uint32_t bo = (uint32_t)(row * 128 + kk * 32 + ((g & 1) * 16));
                uint32_t r0, r1, r2, r3;
                LDSM_X4(r0, r1, r2, r3, sb + 16384 + sw128(bo));
                b[bf*2][0] = r0; b[bf*2][1] = r1;
                b[bf*2+1][0] = r2; b[bf*2+1][1] = r3;
            }
            #pragma unroll
            for (int mf = 0; mf < 4; mf++)
                #pragma unroll
                for (int nf = 0; nf < 4; nf++)
                    MMA16816(acc[mf][nf], a[mf], b[nf]);
        }
    };

    // ---- pipeline: 3 stages, 4 chunks --------------------------------------
    load_stage(0, 0);        // g0
    load_stage(1, 1);        // g1
    load_stage(2, 2);        // g2

    CP_WAIT(2); __syncthreads();       // g0 done
    compute(dynu);
    __syncthreads();                   // everyone done reading stage 0
    load_stage(3, 0);                  // g3

    CP_WAIT(2); __syncthreads();       // g1 done
    compute(dynu + STAGE);

    CP_WAIT(1); __syncthreads();       // g2 done
    compute(dynu + 2 * STAGE);

    CP_WAIT(0); __syncthreads();       // g3 done
    compute(dynu);

    // ---- epilogue: direct fp32 stores --------------------------------------
    #pragma unroll
    for (int mf = 0; mf < 4; mf++) {
        int row = m0 + warp_m * 64 + mf * 16 + (lane >> 2);
        #pragma unroll
        for (int nf = 0; nf < 4; nf++) {
            int col = ncol0 + warp_n * 32 + nf * 8 + 2 * (lane & 3);
            *(float2*)(O + (size_t)row * NCLS + col) =
                make_float2(acc[mf][nf][0], acc[mf][nf][1]);
            *(float2*)(O + (size_t)(row + 8) * NCLS + col) =
                make_float2(acc[mf][nf][2], acc[mf][nf][3]);
        }
    }
}

// ---------------------------------------------------------------------------
// 4) finalize new_db
// ---------------------------------------------------------------------------
__global__ void finalize_kernel(const float* __restrict__ w,
                                const float* __restrict__ e,
                                float* __restrict__ db)
{
    int idx = blockIdx.x * blockDim.x + threadIdx.x;
    if (idx >= DIM * NCLS) return;
    int c = idx & (NCLS - 1);

    float cnt    = g_cnt[c];
    float negAnc = (g_sumA[c]  > 0.5f) ? 1.0f : 0.0f;
    float posAnc = (g_sumNA[c] > 0.5f) ? 1.0f : 0.0f;
    float negCls = (cnt > 0.5f) ? 0.0f : 1.0f;

    float wv = w[idx];
    float ev = e[idx];
    float ema = 0.1f * (g_num[idx] / (cnt + EPS_F));
    db[idx] = ALPHA_F * wv * negAnc + ema + wv * negCls + ev * posAnc;
}

// ---------------------------------------------------------------------------
// launch
// ---------------------------------------------------------------------------
extern "C" void kernel_launch(void* const* d_in, const int* in_sizes, int n_in,
                              void* d_out, int out_size)
{
    const float* emb = (const float*)d_in[0];
    const int*   obj = (const int*)  d_in[2];
    const float* anc = (const float*)d_in[3];
    const float* w   = (const float*)d_in[5];
    const float* e   = (const float*)d_in[6];

    float* out   = (float*)d_out;
    float* o_cls = out;
    float* o_seq = out + (size_t)T_TOKENS * NCLS;
    float* db    = out + (size_t)2 * T_TOKENS * NCLS;

    cudaFuncSetAttribute(gemm_hmma_kernel,
                         cudaFuncAttributeMaxDynamicSharedMemorySize, GEMM_SMEM);

    zero_kernel<<<512, 256>>>();
    norm_x_kernel<<<(T_TOKENS * 32) / 256, 256>>>(emb, obj, anc);
    colsum_kernel<<<dim3(4, 32, 2), 256>>>(w, e);
    build_bt_kernel<<<dim3(32, 8, 2), 256>>>(w, e);

    dim3 grid(T_TOKENS / BM, 2 * NCLS / BN);     // (256, 16)
    gemm_hmma_kernel<<<grid, 256, GEMM_SMEM>>>(o_cls, o_seq);

    finalize_kernel<<<(DIM * NCLS) / 256, 256>>>(w, e, db);
}

// round 7
// speedup vs baseline: 5.8020x; 1.0030x over previous
#include <cuda_runtime.h>
#include <cuda_fp16.h>
#include <cstdint>

// ---------------------------------------------------------------------------
// B=32, N=1024 -> T=32768 tokens, d=256, C=1024
// o_cls (T x C) = l2norm(x) @ l2norm(e,0)
// o_seq (T x C) = l2norm(x) @ l2norm(w,0)
// new_db (d x C) = EMA codebook update
// GEMMs: fp16 mma.sync (HMMA), 3-stage cp.async pipeline.
// ---------------------------------------------------------------------------

#define T_TOKENS 32768
#define DIM      256
#define NCLS     1024
#define ALPHA_F  0.9f
#define EPS_F    1.19e-07f

// GEMM tiling
#define BM 128
#define BN 128
#define BK 64                       // 64 fp16 = 128 bytes/row (SW128 atom)
#define STAGE  32768                // A 16KB + B 16KB
#define GEMM_SMEM (1024 + 3 * STAGE)

// ---------------- device scratch (allocation-free) -------------------------
__device__ __align__(16) __half g_x16 [(size_t)T_TOKENS * DIM];   // normalized x, fp16
__device__ __align__(16) __half g_bt16[(size_t)2 * NCLS * DIM];   // [class][k]: rows 0..1023 = en, 1024..2047 = wn
__device__ float g_num[DIM * NCLS];
__device__ float g_cnt[NCLS];
__device__ float g_sumA[NCLS];
__device__ float g_sumNA[NCLS];
__device__ float g_colsum[2 * NCLS];   // [0..1023]=e column sq-sums, [1024..2047]=w

// ---------------- PTX helpers (portable, sm_80+) ---------------------------
__device__ __forceinline__ uint32_t smem_u32(const void* p) {
    uint32_t a;
    asm("{ .reg .u64 t; cvta.to.shared.u64 t, %1; cvt.u32.u64 %0, t; }" : "=r"(a) : "l"(p));
    return a;
}
__device__ __forceinline__ void cpa16(uint32_t s, const void* g) {
    asm volatile("cp.async.cg.shared.global [%0], [%1], 16;" :: "r"(s), "l"(g));
}
#define CP_COMMIT() asm volatile("cp.async.commit_group;" ::: "memory")
#define CP_WAIT(n)  asm volatile("cp.async.wait_group %0;" :: "n"(n) : "memory")

#define LDSM_X4(r0, r1, r2, r3, addr) \
    asm volatile("ldmatrix.sync.aligned.m8n8.x4.shared.b16 {%0,%1,%2,%3}, [%4];" \
        : "=r"(r0), "=r"(r1), "=r"(r2), "=r"(r3) : "r"(addr))

#define MMA16816(d, a, b) \
    asm volatile("mma.sync.aligned.m16n8k16.row.col.f32.f16.f16.f32 " \
        "{%0,%1,%2,%3},{%4,%5,%6,%7},{%8,%9},{%0,%1,%2,%3};" \
        : "+f"((d)[0]), "+f"((d)[1]), "+f"((d)[2]), "+f"((d)[3]) \
        : "r"((a)[0]), "r"((a)[1]), "r"((a)[2]), "r"((a)[3]), \
          "r"((b)[0]), "r"((b)[1]))

__device__ __forceinline__ uint32_t sw128(uint32_t bo) {
    return bo ^ ((bo >> 3) & 0x70);
}

// ---------------------------------------------------------------------------
// 0) zero accumulators
// ---------------------------------------------------------------------------
__global__ void zero_kernel() {
    int i = blockIdx.x * blockDim.x + threadIdx.x;
    int stride = gridDim.x * blockDim.x;
    for (int j = i; j < DIM * NCLS; j += stride) g_num[j] = 0.0f;
    if (i < 2 * NCLS) g_colsum[i] = 0.0f;
    if (i < NCLS) { g_cnt[i] = 0.0f; g_sumA[i] = 0.0f; g_sumNA[i] = 0.0f; }
}

// ---------------------------------------------------------------------------
// 1) per-token l2 normalize -> fp16 + class-conditioned scatter (fused)
// ---------------------------------------------------------------------------
__global__ void norm_x_kernel(const float* __restrict__ emb,
                              const int*   __restrict__ labels,
                              const float* __restrict__ anc)
{
    int gwarp = (blockIdx.x * blockDim.x + threadIdx.x) >> 5;
    int lane  = threadIdx.x & 31;
    if (gwarp >= T_TOKENS) return;

    const float* src = emb + (size_t)gwarp * DIM + lane * 8;
    float v[8];
    float4 v0 = *(const float4*)(src);
    float4 v1 = *(const float4*)(src + 4);
    v[0]=v0.x; v[1]=v0.y; v[2]=v0.z; v[3]=v0.w;
    v[4]=v1.x; v[5]=v1.y; v[6]=v1.z; v[7]=v1.w;

    float s = 0.f;
    #pragma unroll
    for (int j = 0; j < 8; j++) s += v[j] * v[j];
    #pragma unroll
    for (int o = 16; o > 0; o >>= 1) s += __shfl_xor_sync(0xFFFFFFFFu, s, o);
    float r = rsqrtf(fmaxf(s, 1e-12f));

    union { __half h[8]; float4 f; } H;
    #pragma unroll
    for (int j = 0; j < 8; j++) {
        v[j] *= r;
        H.h[j] = __float2half_rn(v[j]);
    }
    *(float4*)(g_x16 + (size_t)gwarp * DIM + lane * 8) = H.f;

    float a = anc[gwarp];
    int   c = labels[gwarp];
    if (a > 0.5f) {
        int d0 = lane * 8;
        #pragma unroll
        for (int j = 0; j < 8; j++)
            atomicAdd(&g_num[(d0 + j) * NCLS + c], v[j]);
    }
    if (lane == 0) {
        atomicAdd(&g_cnt[c],   1.0f);
        atomicAdd(&g_sumA[c],  a);
        atomicAdd(&g_sumNA[c], 1.0f - a);
    }
}

// ---------------------------------------------------------------------------
// 2a) column squared-sums of e/w (parallel, coalesced)
//     grid (4, 32, 2): x = 256-col block, y = 8-dim block, z = matrix (0=e,1=w)
// ---------------------------------------------------------------------------
__global__ void colsum_kernel(const float* __restrict__ w,
                              const float* __restrict__ e)
{
    const float* src = (blockIdx.z == 0) ? e : w;
    int col = blockIdx.x * 256 + threadIdx.x;
    int d0  = blockIdx.y * 8;
    float s = 0.0f;
    #pragma unroll
    for (int j = 0; j < 8; j++) {
        float v = src[(size_t)(d0 + j) * NCLS + col];
        s += v * v;
    }
    atomicAdd(&g_colsum[blockIdx.z * NCLS + col], s);
}

// ---------------------------------------------------------------------------
// 2b) scale + transpose + fp16 convert: src [d][c] -> g_bt16 [c][d]
//     grid (32, 8, 2): x = 32-col tile, y = 32-dim tile, z = matrix
//     block 256 = (32 cols, 8 rows)
// ---------------------------------------------------------------------------
__global__ void build_bt_kernel(const float* __restrict__ w,
                                const float* __restrict__ e)
{
    __shared__ float tile[32][33];
    __shared__ float rs[32];

    const float* src = (blockIdx.z == 0) ? e : w;
    const int c0 = blockIdx.x * 32;
    const int d0 = blockIdx.y * 32;
    const int tx = threadIdx.x & 31;
    const int ty = threadIdx.x >> 5;

    if (threadIdx.x < 32)
        rs[threadIdx.x] = rsqrtf(fmaxf(g_colsum[blockIdx.z * NCLS + c0 + threadIdx.x], 1e-12f));

    #pragma unroll
    for (int i = 0; i < 4; i++) {
        int dl = ty + i * 8;
        tile[dl][tx] = src[(size_t)(d0 + dl) * NCLS + c0 + tx];
    }
    __syncthreads();

    #pragma unroll
    for (int i = 0; i < 4; i++) {
        int cl = ty + i * 8;
        float v = tile[tx][cl] * rs[cl];
        g_bt16[(size_t)(blockIdx.z * NCLS + c0 + cl) * DIM + d0 + tx] = __float2half_rn(v);
    }
}

// ---------------------------------------------------------------------------
// 3) fp16 HMMA GEMM: tile 128x128, 8 warps (warp tile 64x32), K=256 in
//    4 chunks of 64, 3-stage cp.async pipeline, SW128 smem + ldmatrix.
//    grid = (256, 16): blockIdx.y < 8 -> o_cls, else o_seq.
// ---------------------------------------------------------------------------
__global__ __launch_bounds__(256)
void gemm_hmma_kernel(float* __restrict__ o_cls, float* __restrict__ o_seq)
{
    extern __shared__ char dsm[];
    const int tid    = threadIdx.x;
    const int lane   = tid & 31;
    const int wid    = tid >> 5;
    const int warp_m = wid & 1;     // 0..1 -> rows wm*64
    const int warp_n = wid >> 1;    // 0..3 -> cols wn*32

    const int m0 = blockIdx.x * BM;
    const int n0 = blockIdx.y * BN;              // fused column space [0,2048)
    float* O = (n0 < NCLS) ? o_cls : o_seq;
    const int ncol0 = n0 & (NCLS - 1);

    uint32_t raw  = smem_u32(dsm);
    uint32_t dynu = (raw + 1023u) & ~1023u;

    // ---- stage loader: chunk k0=c*64 -> stage (A @0, B @16384) ------------
    const int lr  = tid >> 3;       // 0..31
    const int lsg = tid & 7;        // 16B segment in row
    auto load_stage = [&](int chunk, int stage) {
        uint32_t sb = dynu + stage * STAGE;
        const int k0 = chunk * BK;
        #pragma unroll
        for (int i = 0; i < 4; i++) {
            int r = lr + i * 32;                 // 0..127
            uint32_t sw = sw128((uint32_t)(r * 128 + lsg * 16));
            cpa16(sb + sw,         g_x16  + (size_t)(m0 + r) * DIM + k0 + lsg * 8);
            cpa16(sb + 16384 + sw, g_bt16 + (size_t)(n0 + r) * DIM + k0 + lsg * 8);
        }
        CP_COMMIT();
    };

    float acc[4][4][4] = {};   // [mfrag][nfrag][4]

    // ---- compute one 64-K chunk from a stage -------------------------------
    auto compute = [&](uint32_t sb) {
        #pragma unroll
        for (int kk = 0; kk < 4; kk++) {         // k16 steps
            uint32_t a[4][4], b[4][2];
            #pragma unroll
            for (int mf = 0; mf < 4; mf++) {
                int row = warp_m * 64 + mf * 16 + (lane & 15);
                uint32_t bo = (uint32_t)(row * 128 + kk * 32 + ((lane >> 4) * 16));
                LDSM_X4(a[mf][0], a[mf][1], a[mf][2], a[mf][3], sb + sw128(bo));
            }
            #pragma unroll
            for (int bf = 0; bf < 2; bf++) {
                int g = lane >> 3;
                int row = warp_n * 32 + bf * 16 + (g >> 1) * 8 + (lane & 7);
                uint32_t bo = (uint32_t)(row * 128 + kk * 32 + ((g & 1) * 16));
                uint32_t r0, r1, r2, r3;
                LDSM_X4(r0, r1, r2, r3, sb + 16384 + sw128(bo));
                b[bf*2][0] = r0; b[bf*2][1] = r1;
                b[bf*2+1][0] = r2; b[bf*2+1][1] = r3;
            }
            #pragma unroll
            for (int mf = 0; mf < 4; mf++)
                #pragma unroll
                for (int nf = 0; nf < 4; nf++)
                    MMA16816(acc[mf][nf], a[mf], b[nf]);
        }
    };

    // ---- pipeline: 3 stages, 4 chunks --------------------------------------
    load_stage(0, 0);        // g0
    load_stage(1, 1);        // g1
    load_stage(2, 2);        // g2

    CP_WAIT(2); __syncthreads();       // g0 done
    compute(dynu);
    __syncthreads();                   // everyone done reading stage 0
    load_stage(3, 0);                  // g3

    CP_WAIT(2); __syncthreads();       // g1 done
    compute(dynu + STAGE);

    CP_WAIT(1); __syncthreads();       // g2 done
    compute(dynu + 2 * STAGE);

    CP_WAIT(0); __syncthreads();       // g3 done
    compute(dynu);

    // ---- epilogue: direct fp32 stores --------------------------------------
    #pragma unroll
    for (int mf = 0; mf < 4; mf++) {
        int row = m0 + warp_m * 64 + mf * 16 + (lane >> 2);
        #pragma unroll
        for (int nf = 0; nf < 4; nf++) {
            int col = ncol0 + warp_n * 32 + nf * 8 + 2 * (lane & 3);
            *(float2*)(O + (size_t)row * NCLS + col) =
                make_float2(acc[mf][nf][0], acc[mf][nf][1]);
            *(float2*)(O + (size_t)(row + 8) * NCLS + col) =
                make_float2(acc[mf][nf][2], acc[mf][nf][3]);
        }
    }
}

// ---------------------------------------------------------------------------
// 4) finalize new_db
// ---------------------------------------------------------------------------
__global__ void finalize_kernel(const float* __restrict__ w,
                                const float* __restrict__ e,
                                float* __restrict__ db)
{
    int idx = blockIdx.x * blockDim.x + threadIdx.x;
    if (idx >= DIM * NCLS) return;
    int c = idx & (NCLS - 1);

    float cnt    = g_cnt[c];
    float negAnc = (g_sumA[c]  > 0.5f) ? 1.0f : 0.0f;
    float posAnc = (g_sumNA[c] > 0.5f) ? 1.0f : 0.0f;
    float negCls = (cnt > 0.5f) ? 0.0f : 1.0f;

    float wv = w[idx];
    float ev = e[idx];
    float ema = 0.1f * (g_num[idx] / (cnt + EPS_F));
    db[idx] = ALPHA_F * wv * negAnc + ema + wv * negCls + ev * posAnc;
}

// ---------------------------------------------------------------------------
// launch
// ---------------------------------------------------------------------------
extern "C" void kernel_launch(void* const* d_in, const int* in_sizes, int n_in,
                              void* d_out, int out_size)
{
    const float* emb = (const float*)d_in[0];
    const int*   obj = (const int*)  d_in[2];
    const float* anc = (const float*)d_in[3];
    const float* w   = (const float*)d_in[5];
    const float* e   = (const float*)d_in[6];

    float* out   = (float*)d_out;
    float* o_cls = out;
    float* o_seq = out + (size_t)T_TOKENS * NCLS;
    float* db    = out + (size_t)2 * T_TOKENS * NCLS;

    cudaFuncSetAttribute(gemm_hmma_kernel,
                         cudaFuncAttributeMaxDynamicSharedMemorySize, GEMM_SMEM);

    zero_kernel<<<512, 256>>>();
    norm_x_kernel<<<(T_TOKENS * 32) / 256, 256>>>(emb, obj, anc);
    colsum_kernel<<<dim3(4, 32, 2), 256>>>(w, e);
    build_bt_kernel<<<dim3(32, 8, 2), 256>>>(w, e);

    dim3 grid(T_TOKENS / BM, 2 * NCLS / BN);     // (256, 16)
    gemm_hmma_kernel<<<grid, 256, GEMM_SMEM>>>(o_cls, o_seq);

    finalize_kernel<<<(DIM * NCLS) / 256, 256>>>(w, e, db);
}